// round 11
// baseline (speedup 1.0000x reference)
#include <cuda_runtime.h>
#include <cuda_fp16.h>
#include <cstdint>

// ===========================================================================
// TreeModel via single-pass fp16 HMMA GEMMs (fp32 accumulate).
// R10: CTA tile 128x256, 8 warps of 64x64 (square warp tile: 128 B/MMA smem
// traffic, 32 MMA per 8 LDSM), 1 CTA/SM, ~200 regs, 3-stage mbarrier pipeline.
// ===========================================================================

#define M_DIM   16384
#define K_DIM   1024
#define N_GATE  1023
#define N_OUT   1000

#define BM      128
#define BN      256
#define BK      64          // 64 fp16 = 128B rows (swizzled)
#define NCHUNKS 16          // 1024 / 64
#define STAGES  3
#define NTHREADS 256

#define A_BYTES (BM * BK * 2)        // 16 KB
#define B_BYTES (BN * BK * 2)        // 32 KB
#define STG_BYTES (A_BYTES + B_BYTES)             // 48 KB
#define TILES_BYTES (STAGES * STG_BYTES)          // 144 KB
#define SMEM_TOTAL  (TILES_BYTES + 64)

// ---- scratch (static device allocations) ----
__device__ float   g_p  [(size_t)M_DIM * 1024];   // gate probabilities (f32)
__device__ __half  g_xh [(size_t)M_DIM * 1024];   // fp16(x)
__device__ __half  g_ph [(size_t)M_DIM * 1024];   // fp16(probs)
__device__ __half  g_wh [1024 * 1024];            // W_gate^T fp16
__device__ __half  g_lh [1024 * 1024];            // leaf^T fp16

__device__ __forceinline__ uint32_t smem_u32(const void* p) {
    uint32_t a;
    asm("{ .reg .u64 t; cvta.to.shared.u64 t, %1; cvt.u32.u64 %0, t; }" : "=r"(a) : "l"(p));
    return a;
}
__device__ __forceinline__ void cp16(uint32_t saddr, const void* gaddr) {
    asm volatile("cp.async.cg.shared.global [%0], [%1], 16;" :: "r"(saddr), "l"(gaddr));
}
__device__ __forceinline__ void ldsm_x4(uint32_t& r0, uint32_t& r1, uint32_t& r2, uint32_t& r3,
                                        uint32_t addr) {
    asm volatile("ldmatrix.sync.aligned.m8n8.x4.shared.b16 {%0,%1,%2,%3}, [%4];"
                 : "=r"(r0), "=r"(r1), "=r"(r2), "=r"(r3) : "r"(addr));
}
__device__ __forceinline__ void mma16816(float* c, const uint32_t* a, uint32_t b0, uint32_t b1) {
    asm("mma.sync.aligned.m16n8k16.row.col.f32.f16.f16.f32 "
        "{%0,%1,%2,%3}, {%4,%5,%6,%7}, {%8,%9}, {%0,%1,%2,%3};"
        : "+f"(c[0]), "+f"(c[1]), "+f"(c[2]), "+f"(c[3])
        : "r"(a[0]), "r"(a[1]), "r"(a[2]), "r"(a[3]), "r"(b0), "r"(b1));
}

// ---- mbarrier helpers ----
#define MBAR_INIT(a, c) \
    asm volatile("mbarrier.init.shared.b64 [%0], %1;" :: "r"(a), "r"(c) : "memory")
#define MBAR_ARRIVE(a) \
    asm volatile("mbarrier.arrive.shared.b64 _, [%0];" :: "r"(a) : "memory")
#define CP_ASYNC_MBAR_ARRIVE(a) \
    asm volatile("cp.async.mbarrier.arrive.noinc.shared::cta.b64 [%0];" :: "r"(a) : "memory")
#define MBAR_WAIT(a, par) do {                                                   \
    uint32_t _m = (a); uint32_t _p = (par); uint32_t _d;                         \
    asm volatile("{\n\t.reg .pred p;\n\t"                                        \
        "mbarrier.try_wait.parity.acquire.cta.shared::cta.b64 p, [%1], %2;\n\t"  \
        "selp.b32 %0, 1, 0, p;\n\t}" : "=r"(_d) : "r"(_m), "r"(_p) : "memory");  \
    if (!_d) {                                                                   \
        asm volatile("{\n\t.reg .pred P1;\n\t"                                   \
            "WL_%=:\n\t"                                                         \
            "mbarrier.try_wait.parity.acquire.cta.shared::cta.b64 P1, [%0], %1, 0x989680;\n\t" \
            "@P1 bra.uni WD_%=;\n\t"                                             \
            "bra.uni WL_%=;\n\t"                                                 \
            "WD_%=:\n\t}" :: "r"(_m), "r"(_p) : "memory");                       \
    } } while (0)

// load one 128x64 A tile + 256x64 B tile into stage `st` (swizzled)
__device__ __forceinline__ void load_tiles(
    uint32_t sbase, int st, int tid, int bm0, int bn0, int k0,
    const __half* __restrict__ A, const __half* __restrict__ B)
{
    const uint32_t sa = sbase + (uint32_t)st * STG_BYTES;
    const uint32_t sb = sa + A_BYTES;
    #pragma unroll
    for (int i = 0; i < 4; i++) {               // A: 128 rows * 8 chunks = 1024
        int idx = i * NTHREADS + tid;
        int row = idx >> 3;
        int ch  = idx & 7;
        uint32_t col = (uint32_t)ch * 16;
        uint32_t sw  = (uint32_t)row * 128 + (col ^ (((uint32_t)row & 7u) << 4));
        cp16(sa + sw, A + (size_t)(bm0 + row) * K_DIM + k0 + ch * 8);
    }
    #pragma unroll
    for (int i = 0; i < 8; i++) {               // B: 256 rows * 8 chunks = 2048
        int idx = i * NTHREADS + tid;
        int row = idx >> 3;
        int ch  = idx & 7;
        uint32_t col = (uint32_t)ch * 16;
        uint32_t sw  = (uint32_t)row * 128 + (col ^ (((uint32_t)row & 7u) << 4));
        cp16(sb + sw, B + (size_t)(bn0 + row) * K_DIM + k0 + ch * 8);
    }
}

// ---------------------------------------------------------------------------
// EPI=1: sigmoid(acc + bias) -> C (ldc=1024)
// EPI=0: acc -> C (ldc=N_OUT, guard col < N_OUT)
// ---------------------------------------------------------------------------
template<int EPI>
__global__ void __launch_bounds__(NTHREADS, 1)
hmma_gemm(const __half* __restrict__ A, const __half* __restrict__ B,
          const float* __restrict__ bias, float* __restrict__ C)
{
    extern __shared__ char smem[];
    const uint32_t sbase = smem_u32(smem);
    const uint32_t mbase = sbase + TILES_BYTES;   // full[s] +s*16, empty[s] +s*16+8
    const int tid  = threadIdx.x;
    const int lane = tid & 31;
    const int wid  = tid >> 5;          // 0..7
    const int wm   = wid & 1;           // 0..1  (m)
    const int wn   = wid >> 1;          // 0..3  (n)
    const int m0w  = wm * 64;
    const int n0w  = wn * 64;
    const int bm0  = blockIdx.y * BM;
    const int bn0  = blockIdx.x * BN;

    if (tid == 0) {
        #pragma unroll
        for (int s = 0; s < STAGES; s++) {
            MBAR_INIT(mbase + s * 16, NTHREADS);       // full
            MBAR_INIT(mbase + s * 16 + 8, NTHREADS);   // empty
        }
    }
    __syncthreads();

    // ldmatrix addressing: addr = rowBase + ((lh*16 + ks*32) ^ swmask)
    const int lr = lane & 15;
    const int lh = lane >> 4;
    const uint32_t sw = ((uint32_t)lr & 7u) << 4;
    uint32_t colX[4];
    #pragma unroll
    for (int ks = 0; ks < 4; ks++)
        colX[ks] = (((uint32_t)lh * 16) + (uint32_t)ks * 32) ^ sw;
    uint32_t aRow[4], bRow[4];
    #pragma unroll
    for (int mt = 0; mt < 4; mt++) aRow[mt] = (uint32_t)(m0w + mt * 16 + lr) * 128;
    #pragma unroll
    for (int p = 0; p < 4; p++)    bRow[p]  = (uint32_t)(n0w + p * 16 + lr) * 128;

    float acc[4][8][4];
    #pragma unroll
    for (int mt = 0; mt < 4; mt++)
        #pragma unroll
        for (int nt = 0; nt < 8; nt++)
            #pragma unroll
            for (int q = 0; q < 4; q++) acc[mt][nt][q] = 0.f;

    // producer cursor (stage 0, phase 1): first empty-waits pass immediately
    int pst = 0, pph = 1;
    #pragma unroll
    for (int pc = 0; pc < 2; pc++) {
        load_tiles(sbase, pst, tid, bm0, bn0, pc * BK, A, B);
        CP_ASYNC_MBAR_ARRIVE(mbase + pst * 16);
        if (++pst == STAGES) { pst = 0; pph ^= 1; }
    }

    int cst = 0, cph = 0;

    #pragma unroll 1
    for (int c = 0; c < NCHUNKS; c++) {
        MBAR_WAIT(mbase + cst * 16, (uint32_t)cph);          // stage cst full

        const int pc = c + 2;
        if (pc < NCHUNKS) {
            MBAR_WAIT(mbase + pst * 16 + 8, (uint32_t)pph);  // stage pst empty
            load_tiles(sbase, pst, tid, bm0, bn0, pc * BK, A, B);
            CP_ASYNC_MBAR_ARRIVE(mbase + pst * 16);
            if (++pst == STAGES) { pst = 0; pph ^= 1; }
        }

        const uint32_t sa = sbase + (uint32_t)cst * STG_BYTES;
        const uint32_t sb = sa + A_BYTES;

        #pragma unroll
        for (int ks = 0; ks < 4; ks++) {
            uint32_t a[4][4];
            #pragma unroll
            for (int mt = 0; mt < 4; mt++)
                ldsm_x4(a[mt][0], a[mt][1], a[mt][2], a[mt][3], sa + aRow[mt] + colX[ks]);
            uint32_t b[8][2];
            #pragma unroll
            for (int p = 0; p < 4; p++) {
                uint32_t r0, r1, r2, r3;
                ldsm_x4(r0, r1, r2, r3, sb + bRow[p] + colX[ks]);
                b[p*2][0] = r0; b[p*2][1] = r2;
                b[p*2+1][0] = r1; b[p*2+1][1] = r3;
            }
            #pragma unroll
            for (int mt = 0; mt < 4; mt++)
                #pragma unroll
                for (int nt = 0; nt < 8; nt++)
                    mma16816(acc[mt][nt], a[mt], b[nt][0], b[nt][1]);
        }

        MBAR_ARRIVE(mbase + cst * 16 + 8);                   // done reading stage cst
        if (++cst == STAGES) { cst = 0; cph ^= 1; }
    }

    // epilogue
    const int gq = lane >> 2;
    const int tq = lane & 3;
    #pragma unroll
    for (int mt = 0; mt < 4; mt++) {
        #pragma unroll
        for (int nt = 0; nt < 8; nt++) {
            const int col = bn0 + n0w + nt * 8 + tq * 2;
            const int r0  = bm0 + m0w + mt * 16 + gq;
            float v0 = acc[mt][nt][0], v1 = acc[mt][nt][1];
            float v2 = acc[mt][nt][2], v3 = acc[mt][nt][3];
            if (EPI == 1) {
                float b0 = (col     < N_GATE) ? bias[col]     : 0.f;
                float b1 = (col + 1 < N_GATE) ? bias[col + 1] : 0.f;
                v0 = 1.f / (1.f + __expf(-(v0 + b0)));
                v1 = 1.f / (1.f + __expf(-(v1 + b1)));
                v2 = 1.f / (1.f + __expf(-(v2 + b0)));
                v3 = 1.f / (1.f + __expf(-(v3 + b1)));
                *(float2*)(C + (size_t)r0 * 1024 + col)       = make_float2(v0, v1);
                *(float2*)(C + (size_t)(r0 + 8) * 1024 + col) = make_float2(v2, v3);
            } else {
                if (col + 1 < N_OUT) {
                    *(float2*)(C + (size_t)r0 * N_OUT + col)       = make_float2(v0, v1);
                    *(float2*)(C + (size_t)(r0 + 8) * N_OUT + col) = make_float2(v2, v3);
                } else if (col < N_OUT) {
                    C[(size_t)r0 * N_OUT + col]       = v0;
                    C[(size_t)(r0 + 8) * N_OUT + col] = v2;
                }
            }
        }
    }
}

// ---------------------------------------------------------------------------
// x: f32 -> fp16
// ---------------------------------------------------------------------------
__global__ void __launch_bounds__(256)
cvt_kernel(const float* __restrict__ in, __half* __restrict__ out, int n4)
{
    int i = blockIdx.x * 256 + threadIdx.x;
    if (i >= n4) return;
    float4 v = ((const float4*)in)[i];
    __half2* O = (__half2*)out;
    O[i*2]   = __floats2half2_rn(v.x, v.y);
    O[i*2+1] = __floats2half2_rn(v.z, v.w);
}

// ---------------------------------------------------------------------------
// transpose + convert: in[1024, Nin] f32 -> [1024(N, zero pad), 1024(K)] fp16
// ---------------------------------------------------------------------------
__global__ void __launch_bounds__(256)
transpose_cvt_kernel(const float* __restrict__ in, int Nin,
                     __half* __restrict__ outT)
{
    __shared__ float t[32][33];
    const int k0 = blockIdx.x * 32, n0 = blockIdx.y * 32;
    const int x = threadIdx.x & 31, y = threadIdx.x >> 5;
    #pragma unroll
    for (int i = 0; i < 32; i += 8) {
        int n = n0 + x;
        t[y + i][x] = (n < Nin) ? in[(size_t)(k0 + y + i) * Nin + n] : 0.f;
    }
    __syncthreads();
    #pragma unroll
    for (int i = 0; i < 32; i += 8) {
        int n = n0 + y + i, k = k0 + x;
        outT[(size_t)n * 1024 + k] = __float2half_rn(t[x][y + i]);
    }
}

// ---------------------------------------------------------------------------
// Tree path-product -> probs as fp16.
// ---------------------------------------------------------------------------
__global__ void __launch_bounds__(256)
tree_kernel()
{
    __shared__ float sp[2][1024];
    const int half = threadIdx.x >> 7;
    const int t    = threadIdx.x & 127;
    const int s    = blockIdx.x * 2 + half;

    const float* prow = g_p + (size_t)s * 1024;
    #pragma unroll
    for (int i = 0; i < 8; i++) {
        int idx = t + i * 128;
        if (idx < N_GATE) sp[half][idx] = prow[idx];
    }
    __syncthreads();

    const float* pr = sp[half];
    const int base = t * 8;

    float pref = 1.0f;
    #pragma unroll
    for (int k = 0; k < 7; k++) {
        int node = (1 << k) - 1 + (base >> (10 - k));
        int bit  = (base >> (9 - k)) & 1;
        float pv = pr[node];
        pref *= bit ? pv : (1.0f - pv);
    }
    float p7 = pr[127 + (base >> 3)];
    float p8[2];
    p8[0] = pr[255 + (base >> 2) + 0];
    p8[1] = pr[255 + (base >> 2) + 1];
    float p9[4];
    #pragma unroll
    for (int i = 0; i < 4; i++) p9[i] = pr[511 + (base >> 1) + i];

    __align__(16) __half H[8];
    #pragma unroll
    for (int j = 0; j < 8; j++) {
        int b2 = (j >> 2) & 1, b1 = (j >> 1) & 1, b0 = j & 1;
        float v = pref * (b2 ? p7 : (1.0f - p7));
        float q8 = p8[b2];
        v *= b1 ? q8 : (1.0f - q8);
        float q9 = p9[j >> 1];
        v *= b0 ? q9 : (1.0f - q9);
        H[j] = __float2half_rn(v);
    }
    *(uint4*)(g_ph + (size_t)s * 1024 + base) = *(uint4*)H;
}

// ---------------------------------------------------------------------------
extern "C" void kernel_launch(void* const* d_in, const int* in_sizes, int n_in,
                              void* d_out, int out_size)
{
    const float* x    = (const float*)d_in[0];
    const float* Wg   = (const float*)d_in[1];
    const float* bg   = (const float*)d_in[2];
    const float* leaf = (const float*)d_in[3];
    float* out = (float*)d_out;

    float *p_ptr;
    __half *xh, *ph, *wh, *lh;
    cudaGetSymbolAddress((void**)&p_ptr, g_p);
    cudaGetSymbolAddress((void**)&xh, g_xh);
    cudaGetSymbolAddress((void**)&ph, g_ph);
    cudaGetSymbolAddress((void**)&wh, g_wh);
    cudaGetSymbolAddress((void**)&lh, g_lh);

    cudaFuncSetAttribute(hmma_gemm<1>, cudaFuncAttributeMaxDynamicSharedMemorySize, SMEM_TOTAL);
    cudaFuncSetAttribute(hmma_gemm<0>, cudaFuncAttributeMaxDynamicSharedMemorySize, SMEM_TOTAL);

    // prep: convert x; transpose+convert weights
    {
        int n4 = (M_DIM * K_DIM) / 4;
        cvt_kernel<<<(n4 + 255) / 256, 256>>>(x, xh, n4);
        dim3 tg(32, 32);
        transpose_cvt_kernel<<<tg, 256>>>(Wg, N_GATE, wh);
        transpose_cvt_kernel<<<tg, 256>>>(leaf, N_OUT, lh);
    }

    // GEMM1 + sigmoid -> g_p
    {
        dim3 grid(1024 / BN, M_DIM / BM);   // (4, 128)
        hmma_gemm<1><<<grid, NTHREADS, SMEM_TOTAL>>>(xh, wh, bg, p_ptr);
    }

    // tree products -> probs fp16
    tree_kernel<<<M_DIM / 2, 256>>>();

    // GEMM2 -> out
    {
        dim3 grid(1024 / BN, M_DIM / BM);   // (4, 128)
        hmma_gemm<0><<<grid, NTHREADS, SMEM_TOTAL>>>(ph, lh, nullptr, out);
    }
}

// round 12
// speedup vs baseline: 1.1655x; 1.1655x over previous
#include <cuda_runtime.h>
#include <cuda_fp16.h>
#include <cstdint>

// ===========================================================================
// TreeModel via single-pass fp16 HMMA GEMMs (fp32 accumulate).
// R11: 24 warps/SM — 3 CTAs x 256 threads, CTA tile 128x64, warp tile 32x32,
// 3-stage mbarrier pipeline. Regs <= 85 via launch_bounds(256,3).
// ===========================================================================

#define M_DIM   16384
#define K_DIM   1024
#define N_GATE  1023
#define N_OUT   1000

#define BM      128
#define BN      64
#define BK      64          // 64 fp16 = 128B rows (swizzled)
#define NCHUNKS 16          // 1024 / 64
#define STAGES  3
#define NTHREADS 256

#define A_BYTES (BM * BK * 2)        // 16 KB
#define B_BYTES (BN * BK * 2)        // 8 KB
#define STG_BYTES (A_BYTES + B_BYTES)             // 24 KB
#define TILES_BYTES (STAGES * STG_BYTES)          // 72 KB
#define SMEM_TOTAL  (TILES_BYTES + 64)

// ---- scratch (static device allocations) ----
__device__ float   g_p  [(size_t)M_DIM * 1024];   // gate probabilities (f32)
__device__ __half  g_xh [(size_t)M_DIM * 1024];   // fp16(x)
__device__ __half  g_ph [(size_t)M_DIM * 1024];   // fp16(probs)
__device__ __half  g_wh [1024 * 1024];            // W_gate^T fp16
__device__ __half  g_lh [1024 * 1024];            // leaf^T fp16

__device__ __forceinline__ uint32_t smem_u32(const void* p) {
    uint32_t a;
    asm("{ .reg .u64 t; cvta.to.shared.u64 t, %1; cvt.u32.u64 %0, t; }" : "=r"(a) : "l"(p));
    return a;
}
__device__ __forceinline__ void cp16(uint32_t saddr, const void* gaddr) {
    asm volatile("cp.async.cg.shared.global [%0], [%1], 16;" :: "r"(saddr), "l"(gaddr));
}
__device__ __forceinline__ void ldsm_x4(uint32_t& r0, uint32_t& r1, uint32_t& r2, uint32_t& r3,
                                        uint32_t addr) {
    asm volatile("ldmatrix.sync.aligned.m8n8.x4.shared.b16 {%0,%1,%2,%3}, [%4];"
                 : "=r"(r0), "=r"(r1), "=r"(r2), "=r"(r3) : "r"(addr));
}
__device__ __forceinline__ void mma16816(float* c, const uint32_t* a, uint32_t b0, uint32_t b1) {
    asm("mma.sync.aligned.m16n8k16.row.col.f32.f16.f16.f32 "
        "{%0,%1,%2,%3}, {%4,%5,%6,%7}, {%8,%9}, {%0,%1,%2,%3};"
        : "+f"(c[0]), "+f"(c[1]), "+f"(c[2]), "+f"(c[3])
        : "r"(a[0]), "r"(a[1]), "r"(a[2]), "r"(a[3]), "r"(b0), "r"(b1));
}

// ---- mbarrier helpers ----
#define MBAR_INIT(a, c) \
    asm volatile("mbarrier.init.shared.b64 [%0], %1;" :: "r"(a), "r"(c) : "memory")
#define MBAR_ARRIVE(a) \
    asm volatile("mbarrier.arrive.shared.b64 _, [%0];" :: "r"(a) : "memory")
#define CP_ASYNC_MBAR_ARRIVE(a) \
    asm volatile("cp.async.mbarrier.arrive.noinc.shared::cta.b64 [%0];" :: "r"(a) : "memory")
#define MBAR_WAIT(a, par) do {                                                   \
    uint32_t _m = (a); uint32_t _p = (par); uint32_t _d;                         \
    asm volatile("{\n\t.reg .pred p;\n\t"                                        \
        "mbarrier.try_wait.parity.acquire.cta.shared::cta.b64 p, [%1], %2;\n\t"  \
        "selp.b32 %0, 1, 0, p;\n\t}" : "=r"(_d) : "r"(_m), "r"(_p) : "memory");  \
    if (!_d) {                                                                   \
        asm volatile("{\n\t.reg .pred P1;\n\t"                                   \
            "WL_%=:\n\t"                                                         \
            "mbarrier.try_wait.parity.acquire.cta.shared::cta.b64 P1, [%0], %1, 0x989680;\n\t" \
            "@P1 bra.uni WD_%=;\n\t"                                             \
            "bra.uni WL_%=;\n\t"                                                 \
            "WD_%=:\n\t}" :: "r"(_m), "r"(_p) : "memory");                       \
    } } while (0)

// load one 128x64 A tile + 64x64 B tile into stage `st` (swizzled)
__device__ __forceinline__ void load_tiles(
    uint32_t sbase, int st, int tid, int bm0, int bn0, int k0,
    const __half* __restrict__ A, const __half* __restrict__ B)
{
    const uint32_t sa = sbase + (uint32_t)st * STG_BYTES;
    const uint32_t sb = sa + A_BYTES;
    #pragma unroll
    for (int i = 0; i < 4; i++) {               // A: 128 rows * 8 chunks = 1024
        int idx = i * NTHREADS + tid;
        int row = idx >> 3;
        int ch  = idx & 7;
        uint32_t col = (uint32_t)ch * 16;
        uint32_t sw  = (uint32_t)row * 128 + (col ^ (((uint32_t)row & 7u) << 4));
        cp16(sa + sw, A + (size_t)(bm0 + row) * K_DIM + k0 + ch * 8);
    }
    #pragma unroll
    for (int i = 0; i < 2; i++) {               // B: 64 rows * 8 chunks = 512
        int idx = i * NTHREADS + tid;
        int row = idx >> 3;
        int ch  = idx & 7;
        uint32_t col = (uint32_t)ch * 16;
        uint32_t sw  = (uint32_t)row * 128 + (col ^ (((uint32_t)row & 7u) << 4));
        cp16(sb + sw, B + (size_t)(bn0 + row) * K_DIM + k0 + ch * 8);
    }
}

// ---------------------------------------------------------------------------
// EPI=1: sigmoid(acc + bias) -> C (ldc=1024)
// EPI=0: acc -> C (ldc=N_OUT, guard col < N_OUT)
// ---------------------------------------------------------------------------
template<int EPI>
__global__ void __launch_bounds__(NTHREADS, 3)
hmma_gemm(const __half* __restrict__ A, const __half* __restrict__ B,
          const float* __restrict__ bias, float* __restrict__ C)
{
    extern __shared__ char smem[];
    const uint32_t sbase = smem_u32(smem);
    const uint32_t mbase = sbase + TILES_BYTES;   // full[s] +s*16, empty[s] +s*16+8
    const int tid  = threadIdx.x;
    const int lane = tid & 31;
    const int wid  = tid >> 5;          // 0..7
    const int wm   = wid & 3;           // 0..3  (m)
    const int wn   = wid >> 2;          // 0..1  (n)
    const int m0w  = wm * 32;
    const int n0w  = wn * 32;
    const int bm0  = blockIdx.y * BM;
    const int bn0  = blockIdx.x * BN;

    if (tid == 0) {
        #pragma unroll
        for (int s = 0; s < STAGES; s++) {
            MBAR_INIT(mbase + s * 16, NTHREADS);       // full
            MBAR_INIT(mbase + s * 16 + 8, NTHREADS);   // empty
        }
    }
    __syncthreads();

    // ldmatrix addressing: addr = rowBase + ((lh*16 + ks*32) ^ swmask)
    const int lr = lane & 15;
    const int lh = lane >> 4;
    const uint32_t sw = ((uint32_t)lr & 7u) << 4;
    uint32_t colX[4];
    #pragma unroll
    for (int ks = 0; ks < 4; ks++)
        colX[ks] = (((uint32_t)lh * 16) + (uint32_t)ks * 32) ^ sw;
    uint32_t aRow[2], bRow[2];
    #pragma unroll
    for (int mt = 0; mt < 2; mt++) aRow[mt] = (uint32_t)(m0w + mt * 16 + lr) * 128;
    #pragma unroll
    for (int p = 0; p < 2; p++)    bRow[p]  = (uint32_t)(n0w + p * 16 + lr) * 128;

    float acc[2][4][4];
    #pragma unroll
    for (int mt = 0; mt < 2; mt++)
        #pragma unroll
        for (int nt = 0; nt < 4; nt++)
            #pragma unroll
            for (int q = 0; q < 4; q++) acc[mt][nt][q] = 0.f;

    // producer cursor (stage 0, phase 1): first empty-waits pass immediately
    int pst = 0, pph = 1;
    #pragma unroll
    for (int pc = 0; pc < 2; pc++) {
        load_tiles(sbase, pst, tid, bm0, bn0, pc * BK, A, B);
        CP_ASYNC_MBAR_ARRIVE(mbase + pst * 16);
        if (++pst == STAGES) { pst = 0; pph ^= 1; }
    }

    int cst = 0, cph = 0;

    #pragma unroll 1
    for (int c = 0; c < NCHUNKS; c++) {
        MBAR_WAIT(mbase + cst * 16, (uint32_t)cph);          // stage cst full

        const int pc = c + 2;
        if (pc < NCHUNKS) {
            MBAR_WAIT(mbase + pst * 16 + 8, (uint32_t)pph);  // stage pst empty
            load_tiles(sbase, pst, tid, bm0, bn0, pc * BK, A, B);
            CP_ASYNC_MBAR_ARRIVE(mbase + pst * 16);
            if (++pst == STAGES) { pst = 0; pph ^= 1; }
        }

        const uint32_t sa = sbase + (uint32_t)cst * STG_BYTES;
        const uint32_t sb = sa + A_BYTES;

        #pragma unroll
        for (int ks = 0; ks < 4; ks++) {
            uint32_t a[2][4];
            #pragma unroll
            for (int mt = 0; mt < 2; mt++)
                ldsm_x4(a[mt][0], a[mt][1], a[mt][2], a[mt][3], sa + aRow[mt] + colX[ks]);
            uint32_t b[4][2];
            #pragma unroll
            for (int p = 0; p < 2; p++) {
                uint32_t r0, r1, r2, r3;
                ldsm_x4(r0, r1, r2, r3, sb + bRow[p] + colX[ks]);
                b[p*2][0] = r0; b[p*2][1] = r2;
                b[p*2+1][0] = r1; b[p*2+1][1] = r3;
            }
            #pragma unroll
            for (int mt = 0; mt < 2; mt++)
                #pragma unroll
                for (int nt = 0; nt < 4; nt++)
                    mma16816(acc[mt][nt], a[mt], b[nt][0], b[nt][1]);
        }

        MBAR_ARRIVE(mbase + cst * 16 + 8);                   // done reading stage cst
        if (++cst == STAGES) { cst = 0; cph ^= 1; }
    }

    // epilogue
    const int gq = lane >> 2;
    const int tq = lane & 3;
    #pragma unroll
    for (int mt = 0; mt < 2; mt++) {
        #pragma unroll
        for (int nt = 0; nt < 4; nt++) {
            const int col = bn0 + n0w + nt * 8 + tq * 2;
            const int r0  = bm0 + m0w + mt * 16 + gq;
            float v0 = acc[mt][nt][0], v1 = acc[mt][nt][1];
            float v2 = acc[mt][nt][2], v3 = acc[mt][nt][3];
            if (EPI == 1) {
                float b0 = (col     < N_GATE) ? bias[col]     : 0.f;
                float b1 = (col + 1 < N_GATE) ? bias[col + 1] : 0.f;
                v0 = 1.f / (1.f + __expf(-(v0 + b0)));
                v1 = 1.f / (1.f + __expf(-(v1 + b1)));
                v2 = 1.f / (1.f + __expf(-(v2 + b0)));
                v3 = 1.f / (1.f + __expf(-(v3 + b1)));
                *(float2*)(C + (size_t)r0 * 1024 + col)       = make_float2(v0, v1);
                *(float2*)(C + (size_t)(r0 + 8) * 1024 + col) = make_float2(v2, v3);
            } else {
                if (col + 1 < N_OUT) {
                    *(float2*)(C + (size_t)r0 * N_OUT + col)       = make_float2(v0, v1);
                    *(float2*)(C + (size_t)(r0 + 8) * N_OUT + col) = make_float2(v2, v3);
                } else if (col < N_OUT) {
                    C[(size_t)r0 * N_OUT + col]       = v0;
                    C[(size_t)(r0 + 8) * N_OUT + col] = v2;
                }
            }
        }
    }
}

// ---------------------------------------------------------------------------
// x: f32 -> fp16
// ---------------------------------------------------------------------------
__global__ void __launch_bounds__(256)
cvt_kernel(const float* __restrict__ in, __half* __restrict__ out, int n4)
{
    int i = blockIdx.x * 256 + threadIdx.x;
    if (i >= n4) return;
    float4 v = ((const float4*)in)[i];
    __half2* O = (__half2*)out;
    O[i*2]   = __floats2half2_rn(v.x, v.y);
    O[i*2+1] = __floats2half2_rn(v.z, v.w);
}

// ---------------------------------------------------------------------------
// transpose + convert: in[1024, Nin] f32 -> [1024(N, zero pad), 1024(K)] fp16
// ---------------------------------------------------------------------------
__global__ void __launch_bounds__(256)
transpose_cvt_kernel(const float* __restrict__ in, int Nin,
                     __half* __restrict__ outT)
{
    __shared__ float t[32][33];
    const int k0 = blockIdx.x * 32, n0 = blockIdx.y * 32;
    const int x = threadIdx.x & 31, y = threadIdx.x >> 5;
    #pragma unroll
    for (int i = 0; i < 32; i += 8) {
        int n = n0 + x;
        t[y + i][x] = (n < Nin) ? in[(size_t)(k0 + y + i) * Nin + n] : 0.f;
    }
    __syncthreads();
    #pragma unroll
    for (int i = 0; i < 32; i += 8) {
        int n = n0 + y + i, k = k0 + x;
        outT[(size_t)n * 1024 + k] = __float2half_rn(t[x][y + i]);
    }
}

// ---------------------------------------------------------------------------
// Tree path-product -> probs as fp16.
// ---------------------------------------------------------------------------
__global__ void __launch_bounds__(256)
tree_kernel()
{
    __shared__ float sp[2][1024];
    const int half = threadIdx.x >> 7;
    const int t    = threadIdx.x & 127;
    const int s    = blockIdx.x * 2 + half;

    const float* prow = g_p + (size_t)s * 1024;
    #pragma unroll
    for (int i = 0; i < 8; i++) {
        int idx = t + i * 128;
        if (idx < N_GATE) sp[half][idx] = prow[idx];
    }
    __syncthreads();

    const float* pr = sp[half];
    const int base = t * 8;

    float pref = 1.0f;
    #pragma unroll
    for (int k = 0; k < 7; k++) {
        int node = (1 << k) - 1 + (base >> (10 - k));
        int bit  = (base >> (9 - k)) & 1;
        float pv = pr[node];
        pref *= bit ? pv : (1.0f - pv);
    }
    float p7 = pr[127 + (base >> 3)];
    float p8[2];
    p8[0] = pr[255 + (base >> 2) + 0];
    p8[1] = pr[255 + (base >> 2) + 1];
    float p9[4];
    #pragma unroll
    for (int i = 0; i < 4; i++) p9[i] = pr[511 + (base >> 1) + i];

    __align__(16) __half H[8];
    #pragma unroll
    for (int j = 0; j < 8; j++) {
        int b2 = (j >> 2) & 1, b1 = (j >> 1) & 1, b0 = j & 1;
        float v = pref * (b2 ? p7 : (1.0f - p7));
        float q8 = p8[b2];
        v *= b1 ? q8 : (1.0f - q8);
        float q9 = p9[j >> 1];
        v *= b0 ? q9 : (1.0f - q9);
        H[j] = __float2half_rn(v);
    }
    *(uint4*)(g_ph + (size_t)s * 1024 + base) = *(uint4*)H;
}

// ---------------------------------------------------------------------------
extern "C" void kernel_launch(void* const* d_in, const int* in_sizes, int n_in,
                              void* d_out, int out_size)
{
    const float* x    = (const float*)d_in[0];
    const float* Wg   = (const float*)d_in[1];
    const float* bg   = (const float*)d_in[2];
    const float* leaf = (const float*)d_in[3];
    float* out = (float*)d_out;

    float *p_ptr;
    __half *xh, *ph, *wh, *lh;
    cudaGetSymbolAddress((void**)&p_ptr, g_p);
    cudaGetSymbolAddress((void**)&xh, g_xh);
    cudaGetSymbolAddress((void**)&ph, g_ph);
    cudaGetSymbolAddress((void**)&wh, g_wh);
    cudaGetSymbolAddress((void**)&lh, g_lh);

    cudaFuncSetAttribute(hmma_gemm<1>, cudaFuncAttributeMaxDynamicSharedMemorySize, SMEM_TOTAL);
    cudaFuncSetAttribute(hmma_gemm<0>, cudaFuncAttributeMaxDynamicSharedMemorySize, SMEM_TOTAL);

    // prep: convert x; transpose+convert weights
    {
        int n4 = (M_DIM * K_DIM) / 4;
        cvt_kernel<<<(n4 + 255) / 256, 256>>>(x, xh, n4);
        dim3 tg(32, 32);
        transpose_cvt_kernel<<<tg, 256>>>(Wg, N_GATE, wh);
        transpose_cvt_kernel<<<tg, 256>>>(leaf, N_OUT, lh);
    }

    // GEMM1 + sigmoid -> g_p
    {
        dim3 grid(1024 / BN, M_DIM / BM);   // (16, 128)
        hmma_gemm<1><<<grid, NTHREADS, SMEM_TOTAL>>>(xh, wh, bg, p_ptr);
    }

    // tree products -> probs fp16
    tree_kernel<<<M_DIM / 2, 256>>>();

    // GEMM2 -> out
    {
        dim3 grid(1024 / BN, M_DIM / BM);   // (16, 128)
        hmma_gemm<0><<<grid, NTHREADS, SMEM_TOTAL>>>(ph, lh, nullptr, out);
    }
}

// round 13
// speedup vs baseline: 1.2976x; 1.1133x over previous
#include <cuda_runtime.h>
#include <cuda_fp16.h>
#include <cstdint>
#include <cstddef>

// ===========================================================================
// TreeModel via single-pass fp16 HMMA GEMMs (fp32 accumulate).
// R12: R8 config (128x128x64, 3-stage mbarrier pipeline, 2 CTAs x 256thr)
// + hoisted cp.async addressing (precomputed smem offsets, incrementing
// global pointers, uniform A->B delta) to cut ALU issue traffic.
// ===========================================================================

#define M_DIM   16384
#define K_DIM   1024
#define N_GATE  1023
#define N_OUT   1000

#define BM      128
#define BN      128
#define BK      64          // 64 fp16 = 128B rows (swizzled)
#define NCHUNKS 16          // 1024 / 64
#define STAGES  3

#define A_BYTES (BM * BK * 2)        // 16 KB
#define B_BYTES (BN * BK * 2)        // 16 KB
#define STG_BYTES (A_BYTES + B_BYTES)
#define TILES_BYTES (STAGES * STG_BYTES)          // 96 KB
#define SMEM_TOTAL  (TILES_BYTES + 64)

// ---- scratch (static device allocations) ----
__device__ float   g_p  [(size_t)M_DIM * 1024];   // gate probabilities (f32)
__device__ __half  g_xh [(size_t)M_DIM * 1024];   // fp16(x)
__device__ __half  g_ph [(size_t)M_DIM * 1024];   // fp16(probs)
__device__ __half  g_wh [1024 * 1024];            // W_gate^T fp16
__device__ __half  g_lh [1024 * 1024];            // leaf^T fp16

__device__ __forceinline__ uint32_t smem_u32(const void* p) {
    uint32_t a;
    asm("{ .reg .u64 t; cvta.to.shared.u64 t, %1; cvt.u32.u64 %0, t; }" : "=r"(a) : "l"(p));
    return a;
}
__device__ __forceinline__ void cp16(uint32_t saddr, const void* gaddr) {
    asm volatile("cp.async.cg.shared.global [%0], [%1], 16;" :: "r"(saddr), "l"(gaddr));
}
__device__ __forceinline__ void ldsm_x4(uint32_t& r0, uint32_t& r1, uint32_t& r2, uint32_t& r3,
                                        uint32_t addr) {
    asm volatile("ldmatrix.sync.aligned.m8n8.x4.shared.b16 {%0,%1,%2,%3}, [%4];"
                 : "=r"(r0), "=r"(r1), "=r"(r2), "=r"(r3) : "r"(addr));
}
__device__ __forceinline__ void mma16816(float* c, const uint32_t* a, uint32_t b0, uint32_t b1) {
    asm("mma.sync.aligned.m16n8k16.row.col.f32.f16.f16.f32 "
        "{%0,%1,%2,%3}, {%4,%5,%6,%7}, {%8,%9}, {%0,%1,%2,%3};"
        : "+f"(c[0]), "+f"(c[1]), "+f"(c[2]), "+f"(c[3])
        : "r"(a[0]), "r"(a[1]), "r"(a[2]), "r"(a[3]), "r"(b0), "r"(b1));
}

// ---- mbarrier helpers ----
#define MBAR_INIT(a, c) \
    asm volatile("mbarrier.init.shared.b64 [%0], %1;" :: "r"(a), "r"(c) : "memory")
#define MBAR_ARRIVE(a) \
    asm volatile("mbarrier.arrive.shared.b64 _, [%0];" :: "r"(a) : "memory")
#define CP_ASYNC_MBAR_ARRIVE(a) \
    asm volatile("cp.async.mbarrier.arrive.noinc.shared::cta.b64 [%0];" :: "r"(a) : "memory")
#define MBAR_WAIT(a, par) do {                                                   \
    uint32_t _m = (a); uint32_t _p = (par); uint32_t _d;                         \
    asm volatile("{\n\t.reg .pred p;\n\t"                                        \
        "mbarrier.try_wait.parity.acquire.cta.shared::cta.b64 p, [%1], %2;\n\t"  \
        "selp.b32 %0, 1, 0, p;\n\t}" : "=r"(_d) : "r"(_m), "r"(_p) : "memory");  \
    if (!_d) {                                                                   \
        asm volatile("{\n\t.reg .pred P1;\n\t"                                   \
            "WL_%=:\n\t"                                                         \
            "mbarrier.try_wait.parity.acquire.cta.shared::cta.b64 P1, [%0], %1, 0x989680;\n\t" \
            "@P1 bra.uni WD_%=;\n\t"                                             \
            "bra.uni WL_%=;\n\t"                                                 \
            "WD_%=:\n\t}" :: "r"(_m), "r"(_p) : "memory");                       \
    } } while (0)

// ---------------------------------------------------------------------------
// EPI=1: sigmoid(acc + bias) -> C (ldc=1024)
// EPI=0: acc -> C (ldc=N_OUT, guard col < N_OUT)
// ---------------------------------------------------------------------------
template<int EPI>
__global__ void __launch_bounds__(256, 2)
hmma_gemm(const __half* __restrict__ A, const __half* __restrict__ B,
          const float* __restrict__ bias, float* __restrict__ C)
{
    extern __shared__ char smem[];
    const uint32_t sbase = smem_u32(smem);
    const uint32_t mbase = sbase + TILES_BYTES;   // full[s] +s*16, empty[s] +s*16+8
    const int tid  = threadIdx.x;
    const int lane = tid & 31;
    const int wid  = tid >> 5;
    const int wm   = wid >> 1;          // 0..3
    const int wn   = wid & 1;           // 0..1
    const int m0w  = wm * 32;
    const int n0w  = wn * 64;
    const int bm0  = blockIdx.y * BM;
    const int bn0  = blockIdx.x * BN;

    if (tid == 0) {
        #pragma unroll
        for (int s = 0; s < STAGES; s++) {
            MBAR_INIT(mbase + s * 16, 256);       // full: 256 cp-group arrivals
            MBAR_INIT(mbase + s * 16 + 8, 256);   // empty: 256 thread arrivals
        }
    }
    __syncthreads();

    // ---- hoisted loader state: 4 swizzled smem offsets + 4 A ptrs + uniform delta
    uint32_t swOff[4];
    const char* gA[4];
    const ptrdiff_t bd = ((const char*)B - (const char*)A)
                       + (ptrdiff_t)(bn0 - bm0) * (K_DIM * 2);
    #pragma unroll
    for (int i = 0; i < 4; i++) {
        int idx = i * 256 + tid;                 // 0..1023
        int row = idx >> 3;                      // 0..127
        int ch  = idx & 7;                       // 16B chunk in row
        uint32_t col = (uint32_t)ch * 16;
        swOff[i] = (uint32_t)row * 128 + (col ^ (((uint32_t)row & 7u) << 4));
        gA[i] = (const char*)(A + (size_t)(bm0 + row) * K_DIM) + ch * 16;
    }

    // ldmatrix addressing: addr = rowBase + ((lh*16 + ks*32) ^ swmask)
    const int lr = lane & 15;
    const int lh = lane >> 4;
    const uint32_t sw = ((uint32_t)lr & 7u) << 4;
    uint32_t colX[4];
    #pragma unroll
    for (int ks = 0; ks < 4; ks++)
        colX[ks] = (((uint32_t)lh * 16) + (uint32_t)ks * 32) ^ sw;
    uint32_t aRow[2], bRow[4];
    #pragma unroll
    for (int mt = 0; mt < 2; mt++) aRow[mt] = (uint32_t)(m0w + mt * 16 + lr) * 128;
    #pragma unroll
    for (int p = 0; p < 4; p++)    bRow[p]  = (uint32_t)(n0w + p * 16 + lr) * 128;

    float acc[2][8][4];
    #pragma unroll
    for (int mt = 0; mt < 2; mt++)
        #pragma unroll
        for (int nt = 0; nt < 8; nt++)
            #pragma unroll
            for (int q = 0; q < 4; q++) acc[mt][nt][q] = 0.f;

    // producer cursor (stage 0, phase 1): first empty-waits pass immediately
    int pst = 0, pph = 1;
    #pragma unroll
    for (int pc = 0; pc < 2; pc++) {
        const uint32_t sa = sbase + (uint32_t)pst * STG_BYTES;
        const uint32_t sb = sa + A_BYTES;
        #pragma unroll
        for (int i = 0; i < 4; i++) {
            cp16(sa + swOff[i], gA[i]);
            cp16(sb + swOff[i], gA[i] + bd);
            gA[i] += BK * 2;
        }
        CP_ASYNC_MBAR_ARRIVE(mbase + pst * 16);
        if (++pst == STAGES) { pst = 0; pph ^= 1; }
    }

    int cst = 0, cph = 0;

    #pragma unroll 1
    for (int c = 0; c < NCHUNKS; c++) {
        MBAR_WAIT(mbase + cst * 16, (uint32_t)cph);          // stage cst full

        if (c + 2 < NCHUNKS) {
            MBAR_WAIT(mbase + pst * 16 + 8, (uint32_t)pph);  // stage pst empty
            const uint32_t sa = sbase + (uint32_t)pst * STG_BYTES;
            const uint32_t sb = sa + A_BYTES;
            #pragma unroll
            for (int i = 0; i < 4; i++) {
                cp16(sa + swOff[i], gA[i]);
                cp16(sb + swOff[i], gA[i] + bd);
                gA[i] += BK * 2;
            }
            CP_ASYNC_MBAR_ARRIVE(mbase + pst * 16);
            if (++pst == STAGES) { pst = 0; pph ^= 1; }
        }

        const uint32_t sa = sbase + (uint32_t)cst * STG_BYTES;
        const uint32_t sb = sa + A_BYTES;

        #pragma unroll
        for (int ks = 0; ks < 4; ks++) {
            uint32_t a[2][4];
            #pragma unroll
            for (int mt = 0; mt < 2; mt++)
                ldsm_x4(a[mt][0], a[mt][1], a[mt][2], a[mt][3], sa + aRow[mt] + colX[ks]);
            uint32_t b[8][2];
            #pragma unroll
            for (int p = 0; p < 4; p++) {
                uint32_t r0, r1, r2, r3;
                ldsm_x4(r0, r1, r2, r3, sb + bRow[p] + colX[ks]);
                b[p*2][0] = r0; b[p*2][1] = r2;
                b[p*2+1][0] = r1; b[p*2+1][1] = r3;
            }
            #pragma unroll
            for (int mt = 0; mt < 2; mt++)
                #pragma unroll
                for (int nt = 0; nt < 8; nt++)
                    mma16816(acc[mt][nt], a[mt], b[nt][0], b[nt][1]);
        }

        MBAR_ARRIVE(mbase + cst * 16 + 8);                   // done reading stage cst
        if (++cst == STAGES) { cst = 0; cph ^= 1; }
    }

    // epilogue
    const int gq = lane >> 2;
    const int tq = lane & 3;
    #pragma unroll
    for (int mt = 0; mt < 2; mt++) {
        #pragma unroll
        for (int nt = 0; nt < 8; nt++) {
            const int col = bn0 + n0w + nt * 8 + tq * 2;
            const int r0  = bm0 + m0w + mt * 16 + gq;
            float v0 = acc[mt][nt][0], v1 = acc[mt][nt][1];
            float v2 = acc[mt][nt][2], v3 = acc[mt][nt][3];
            if (EPI == 1) {
                float b0 = (col     < N_GATE) ? bias[col]     : 0.f;
                float b1 = (col + 1 < N_GATE) ? bias[col + 1] : 0.f;
                v0 = 1.f / (1.f + __expf(-(v0 + b0)));
                v1 = 1.f / (1.f + __expf(-(v1 + b1)));
                v2 = 1.f / (1.f + __expf(-(v2 + b0)));
                v3 = 1.f / (1.f + __expf(-(v3 + b1)));
                *(float2*)(C + (size_t)r0 * 1024 + col)       = make_float2(v0, v1);
                *(float2*)(C + (size_t)(r0 + 8) * 1024 + col) = make_float2(v2, v3);
            } else {
                if (col + 1 < N_OUT) {
                    *(float2*)(C + (size_t)r0 * N_OUT + col)       = make_float2(v0, v1);
                    *(float2*)(C + (size_t)(r0 + 8) * N_OUT + col) = make_float2(v2, v3);
                } else if (col < N_OUT) {
                    C[(size_t)r0 * N_OUT + col]       = v0;
                    C[(size_t)(r0 + 8) * N_OUT + col] = v2;
                }
            }
        }
    }
}

// ---------------------------------------------------------------------------
// x: f32 -> fp16
// ---------------------------------------------------------------------------
__global__ void __launch_bounds__(256)
cvt_kernel(const float* __restrict__ in, __half* __restrict__ out, int n4)
{
    int i = blockIdx.x * 256 + threadIdx.x;
    if (i >= n4) return;
    float4 v = ((const float4*)in)[i];
    __half2* O = (__half2*)out;
    O[i*2]   = __floats2half2_rn(v.x, v.y);
    O[i*2+1] = __floats2half2_rn(v.z, v.w);
}

// ---------------------------------------------------------------------------
// transpose + convert: in[1024, Nin] f32 -> [1024(N, zero pad), 1024(K)] fp16
// ---------------------------------------------------------------------------
__global__ void __launch_bounds__(256)
transpose_cvt_kernel(const float* __restrict__ in, int Nin,
                     __half* __restrict__ outT)
{
    __shared__ float t[32][33];
    const int k0 = blockIdx.x * 32, n0 = blockIdx.y * 32;
    const int x = threadIdx.x & 31, y = threadIdx.x >> 5;
    #pragma unroll
    for (int i = 0; i < 32; i += 8) {
        int n = n0 + x;
        t[y + i][x] = (n < Nin) ? in[(size_t)(k0 + y + i) * Nin + n] : 0.f;
    }
    __syncthreads();
    #pragma unroll
    for (int i = 0; i < 32; i += 8) {
        int n = n0 + y + i, k = k0 + x;
        outT[(size_t)n * 1024 + k] = __float2half_rn(t[x][y + i]);
    }
}

// ---------------------------------------------------------------------------
// Tree path-product -> probs as fp16.
// ---------------------------------------------------------------------------
__global__ void __launch_bounds__(256)
tree_kernel()
{
    __shared__ float sp[2][1024];
    const int half = threadIdx.x >> 7;
    const int t    = threadIdx.x & 127;
    const int s    = blockIdx.x * 2 + half;

    const float* prow = g_p + (size_t)s * 1024;
    #pragma unroll
    for (int i = 0; i < 8; i++) {
        int idx = t + i * 128;
        if (idx < N_GATE) sp[half][idx] = prow[idx];
    }
    __syncthreads();

    const float* pr = sp[half];
    const int base = t * 8;

    float pref = 1.0f;
    #pragma unroll
    for (int k = 0; k < 7; k++) {
        int node = (1 << k) - 1 + (base >> (10 - k));
        int bit  = (base >> (9 - k)) & 1;
        float pv = pr[node];
        pref *= bit ? pv : (1.0f - pv);
    }
    float p7 = pr[127 + (base >> 3)];
    float p8[2];
    p8[0] = pr[255 + (base >> 2) + 0];
    p8[1] = pr[255 + (base >> 2) + 1];
    float p9[4];
    #pragma unroll
    for (int i = 0; i < 4; i++) p9[i] = pr[511 + (base >> 1) + i];

    __align__(16) __half H[8];
    #pragma unroll
    for (int j = 0; j < 8; j++) {
        int b2 = (j >> 2) & 1, b1 = (j >> 1) & 1, b0 = j & 1;
        float v = pref * (b2 ? p7 : (1.0f - p7));
        float q8 = p8[b2];
        v *= b1 ? q8 : (1.0f - q8);
        float q9 = p9[j >> 1];
        v *= b0 ? q9 : (1.0f - q9);
        H[j] = __float2half_rn(v);
    }
    *(uint4*)(g_ph + (size_t)s * 1024 + base) = *(uint4*)H;
}

// ---------------------------------------------------------------------------
extern "C" void kernel_launch(void* const* d_in, const int* in_sizes, int n_in,
                              void* d_out, int out_size)
{
    const float* x    = (const float*)d_in[0];
    const float* Wg   = (const float*)d_in[1];
    const float* bg   = (const float*)d_in[2];
    const float* leaf = (const float*)d_in[3];
    float* out = (float*)d_out;

    float *p_ptr;
    __half *xh, *ph, *wh, *lh;
    cudaGetSymbolAddress((void**)&p_ptr, g_p);
    cudaGetSymbolAddress((void**)&xh, g_xh);
    cudaGetSymbolAddress((void**)&ph, g_ph);
    cudaGetSymbolAddress((void**)&wh, g_wh);
    cudaGetSymbolAddress((void**)&lh, g_lh);

    cudaFuncSetAttribute(hmma_gemm<1>, cudaFuncAttributeMaxDynamicSharedMemorySize, SMEM_TOTAL);
    cudaFuncSetAttribute(hmma_gemm<0>, cudaFuncAttributeMaxDynamicSharedMemorySize, SMEM_TOTAL);

    // prep: convert x; transpose+convert weights
    {
        int n4 = (M_DIM * K_DIM) / 4;
        cvt_kernel<<<(n4 + 255) / 256, 256>>>(x, xh, n4);
        dim3 tg(32, 32);
        transpose_cvt_kernel<<<tg, 256>>>(Wg, N_GATE, wh);
        transpose_cvt_kernel<<<tg, 256>>>(leaf, N_OUT, lh);
    }

    // GEMM1 + sigmoid -> g_p
    {
        dim3 grid(1024 / BN, M_DIM / BM);   // (8, 128)
        hmma_gemm<1><<<grid, 256, SMEM_TOTAL>>>(xh, wh, bg, p_ptr);
    }

    // tree products -> probs fp16
    tree_kernel<<<M_DIM / 2, 256>>>();

    // GEMM2 -> out
    {
        dim3 grid(1024 / BN, M_DIM / BM);   // (8, 128)
        hmma_gemm<0><<<grid, 256, SMEM_TOTAL>>>(ph, lh, nullptr, out);
    }
}